// round 6
// baseline (speedup 1.0000x reference)
#include <cuda_runtime.h>
#include <cuda_fp16.h>
#include <math.h>

#define NNOD 8
#define NEDGE 34
#define ISIZE 512
#define NHEAD 8
#define BB 4
#define SLEN 1024
#define NROWS (BB*SLEN)
#define BSD (NROWS*ISIZE)
#define EPSF 1e-6f
#define WELEM (ISIZE*ISIZE)
#define NMAT (NEDGE + NNOD*4)
#define NW_TOT (NMAT * WELEM)
#define SCORE_N (BB*NHEAD*SLEN*SLEN)
#define GEMM_SMEM 98304

struct Route {
    int act, lind, snode, nsrc;
    int qsel, ksel, vsel;
    int q_in, q_e, q_op;
    int k_in, k_e, k_op;
    int v_in, v_e, v_op;
    int ktype;
    float aw, qw, kw, vw;
};

__device__ Route g_route[NNOD];
__device__ int   g_proc[NNOD];
__device__ int   g_wneed[NMAT];

__device__ float g_outs[NNOD][BSD];
__device__ float g_q[BSD], g_k[BSD], g_v[BSD];
__device__ float g_t0[BSD], g_t1[BSD], g_t2[BSD], g_t3[BSD];
__device__ float g_scores[SCORE_N];
__device__ __half g_Qh[BSD], g_Ql[BSD], g_Kh[BSD], g_Kl[BSD], g_Vh[BSD], g_Vl[BSD];
__device__ __half g_Ph[SCORE_N], g_Pl[SCORE_N];
__device__ __half g_Wh[NW_TOT], g_Wl[NW_TOT];

// ---------------------------------------------------------------- helpers
__device__ __forceinline__ float gelu_f(float x) {
    const float c0 = 0.7978845608028654f, c1 = 0.044715f;
    float x3 = x * x * x;
    return 0.5f * x * (1.f + tanhf(c0 * (x + c1 * x3)));
}
__device__ __forceinline__ const float* sel_in(int inn, const float* ie, const float* io) {
    if (inn == -2) return ie;
    if (inn == -1) return io;
    return g_outs[inn];
}
__device__ __forceinline__ void cp_async16(unsigned saddr, const void* gptr) {
    asm volatile("cp.async.cg.shared.global [%0], [%1], 16;\n" :: "r"(saddr), "l"(gptr));
}
template<int N> __device__ __forceinline__ void cp_wait() {
    asm volatile("cp.async.wait_group %0;\n" :: "n"(N));
}
__device__ __forceinline__ void cp_commit() {
    asm volatile("cp.async.commit_group;\n");
}
__device__ __forceinline__ void ldmx4(unsigned* r, unsigned addr) {
    asm volatile("ldmatrix.sync.aligned.m8n8.x4.shared.b16 {%0,%1,%2,%3}, [%4];\n"
        : "=r"(r[0]), "=r"(r[1]), "=r"(r[2]), "=r"(r[3]) : "r"(addr));
}
__device__ __forceinline__ void ldmx4t(unsigned* r, unsigned addr) {
    asm volatile("ldmatrix.sync.aligned.m8n8.x4.trans.shared.b16 {%0,%1,%2,%3}, [%4];\n"
        : "=r"(r[0]), "=r"(r[1]), "=r"(r[2]), "=r"(r[3]) : "r"(addr));
}
__device__ __forceinline__ void mma16816(float* c, const unsigned* a, const unsigned* b) {
    asm volatile(
        "mma.sync.aligned.m16n8k16.row.col.f32.f16.f16.f32 "
        "{%0,%1,%2,%3}, {%4,%5,%6,%7}, {%8,%9}, {%0,%1,%2,%3};\n"
        : "+f"(c[0]), "+f"(c[1]), "+f"(c[2]), "+f"(c[3])
        : "r"(a[0]), "r"(a[1]), "r"(a[2]), "r"(a[3]), "r"(b[0]), "r"(b[1]));
}

// ---------------------------------------------------------------- routing
__global__ void route_kernel(const float* __restrict__ node_p,
                             const float* __restrict__ edge_p) {
    if (threadIdx.x != 0 || blockIdx.x != 0) return;
    for (int i = 0; i < NNOD; i++) g_proc[i] = 0;
    for (int i = 0; i < NMAT; i++) g_wneed[i] = 0;
    int lind = 0;
    for (int c = 0; c < NNOD; c++) {
        Route r;
        r.lind = lind;
        int nsrc = (c + 2 < 5) ? c + 2 : 5;
        r.nsrc = nsrc;
        int snode = c - nsrc;
        r.snode = snode;
        int nL = nsrc * 5;

        const float* np = node_p + c * 8;
        int act = 0;
        for (int j = 1; j < 8; j++) if (np[j] > np[act]) act = j;
        float mx = np[0];
        for (int j = 1; j < 8; j++) mx = fmaxf(mx, np[j]);
        float ssum = 0.f;
        for (int j = 0; j < 8; j++) ssum += expf(np[j] - mx);
        r.act = act;
        r.aw = expf(np[act] - mx) / ssum;

        const float* epq = edge_p + 0 * NEDGE * 5 + lind * 5;
        const float* epk = edge_p + 1 * NEDGE * 5 + lind * 5;
        const float* epv = edge_p + 2 * NEDGE * 5 + lind * 5;

        int qsel = 5;
        for (int j = 6; j < nL; j++) if (epq[j] > epq[qsel]) qsel = j;
        {
            float m2 = epq[5];
            for (int j = 6; j < nL; j++) m2 = fmaxf(m2, epq[j]);
            float ss = 0.f;
            for (int j = 5; j < nL; j++) ss += expf(epq[j] - m2);
            r.qw = expf(epq[qsel] - m2) / ss;
        }
        r.qsel = qsel;
        r.ksel = -1; r.vsel = -1; r.kw = 0.f; r.vw = 0.f; r.ktype = 0;
        r.k_in = 0; r.k_e = 0; r.k_op = 0; r.v_in = 0; r.v_e = 0; r.v_op = 0;

        int use_km = (act > 0);
        if (act < 7) {
            int st = use_km ? 5 : 0;
            int ks = st;
            for (int j = st + 1; j < nL; j++) if (epk[j] > epk[ks]) ks = j;
            float m2 = epk[st];
            for (int j = st + 1; j < nL; j++) m2 = fmaxf(m2, epk[j]);
            float ss = 0.f;
            for (int j = st; j < nL; j++) ss += expf(epk[j] - m2);
            r.ksel = ks;
            r.kw = expf(epk[ks] - m2) / ss;
            r.ktype = (ks / 5 == 0) ? -2 : -1;
            if (act < 5) {
                if (act == 0 && r.ktype == -2) {
                    int vs = 0;
                    for (int j = 1; j < 5; j++) if (epv[j] > epv[vs]) vs = j;
                    float m3 = epv[0];
                    for (int j = 1; j < 5; j++) m3 = fmaxf(m3, epv[j]);
                    float s3 = 0.f;
                    for (int j = 0; j < 5; j++) s3 += expf(epv[j] - m3);
                    r.vsel = vs;
                    r.vw = expf(epv[vs] - m3) / s3;
                } else {
                    int vs = st;
                    for (int j = st + 1; j < nL; j++) if (epv[j] > epv[vs]) vs = j;
                    float m3 = epv[st];
                    for (int j = st + 1; j < nL; j++) m3 = fmaxf(m3, epv[j]);
                    float s3 = 0.f;
                    for (int j = st; j < nL; j++) s3 += expf(epv[j] - m3);
                    r.vsel = vs;
                    r.vw = expf(epv[vs] - m3) / s3;
                }
            }
        }
        int se = qsel / 5;
        r.q_op = qsel % 5; r.q_e = lind + se;
        r.q_in = (se == 0) ? -2 : snode + se;
        if (r.q_in >= 0) g_proc[r.q_in] = 1;
        if (r.q_op < 4) g_wneed[r.q_e] = 1;
        if (r.ksel >= 0) {
            se = r.ksel / 5; r.k_op = r.ksel % 5; r.k_e = lind + se;
            r.k_in = (se == 0) ? -2 : snode + se;
            if (r.k_in >= 0) g_proc[r.k_in] = 1;
            if (r.k_op < 4) g_wneed[r.k_e] = 1;
        }
        if (r.vsel >= 0) {
            se = r.vsel / 5; r.v_op = r.vsel % 5; r.v_e = lind + se;
            r.v_in = (se == 0) ? -2 : snode + se;
            if (r.v_in >= 0) g_proc[r.v_in] = 1;
            if (r.v_op < 4) g_wneed[r.v_e] = 1;
        }
        int nb0 = NEDGE + c * 4;
        if (act == 0) { g_wneed[nb0]=1; g_wneed[nb0+1]=1; g_wneed[nb0+2]=1; g_wneed[nb0+3]=1; }
        else if (act == 1) { g_wneed[nb0]=1; g_wneed[nb0+1]=1; g_wneed[nb0+3]=1; }
        else if (act == 3) { g_wneed[nb0]=1; g_wneed[nb0+1]=1; g_wneed[nb0+2]=1; g_wneed[nb0+3]=1; }
        else if (act == 5) { g_wneed[nb0+1]=1; }
        g_route[c] = r;
        lind += nsrc;
    }
}

// ---------------------------------------------------------------- gated weight split
__global__ void wsplit_kernel(const float* __restrict__ eW, const float* __restrict__ nW) {
    int m = blockIdx.y;
    if (!g_wneed[m]) return;
    size_t base = (size_t)m * WELEM;
    const float* src = (m < NEDGE) ? (eW + base) : (nW + base - (size_t)NEDGE * WELEM);
    for (int i = blockIdx.x * blockDim.x + threadIdx.x; i < WELEM; i += gridDim.x * blockDim.x) {
        float v = src[i];
        __half h = __float2half_rn(v);
        g_Wh[base + i] = h;
        g_Wl[base + i] = __float2half_rn(v - __half2float(h));
    }
}

// ---------------------------------------------------------------- stage resolve
struct Cfg {
    const float* A;
    float* outf; __half* outh; __half* outl;
    const float* bias; const float* res; const float* g; const float* be;
    size_t wb; float scale;
    int use_ln, actc, copy, comb;
};

__device__ bool resolve2(int node, int set, int z,
    const float* ie, const float* io,
    const float* eb, const float* eg, const float* ebe,
    const float* nb, const float* ng, const float* nbe, Cfg& c) {
    const Route r = g_route[node];
    c.A = nullptr; c.outf = nullptr; c.outh = nullptr; c.outl = nullptr;
    c.bias = nullptr; c.res = nullptr; c.g = nullptr; c.be = nullptr;
    c.wb = 0; c.scale = 1.f; c.use_ln = 0; c.actc = 0; c.copy = 0; c.comb = 0;
    if (set == 0) {
        int sel, e, op, inn; float w; float* out;
        if (z == 0) { sel = r.qsel; e = r.q_e; op = r.q_op; inn = r.q_in; w = r.qw; out = g_q; }
        else if (z == 1) { sel = r.ksel; e = r.k_e; op = r.k_op; inn = r.k_in; w = r.kw; out = g_k; }
        else { sel = r.vsel; e = r.v_e; op = r.v_op; inn = r.v_in; w = r.vw; out = g_v; }
        if (sel < 0) return false;
        c.A = sel_in(inn, ie, io); c.outf = out; c.scale = w;
        if (op == 4) { c.copy = 1; return true; }
        c.wb = (size_t)e * WELEM;
        c.bias = eb + e * ISIZE;
        if (op < 3) {
            c.use_ln = 1; c.g = eg + e * ISIZE; c.be = ebe + e * ISIZE;
            c.actc = (op == 0) ? 1 : (op == 1) ? 2 : 0;
        }
        return true;
    }
    int a = r.act;
    size_t nwb0 = (size_t)(NEDGE + node * 4) * WELEM;
    if (set == 1) {
        if (z == 0) {
            if (a != 0 && a != 1 && a != 3) return false;
            c.A = g_q; c.wb = nwb0;
            if (a == 0) { c.use_ln = 1; c.g = ng + node * ISIZE; c.be = nbe + node * ISIZE;
                          c.bias = nb + (node * 4) * ISIZE; c.outh = g_Qh; c.outl = g_Ql; }
            else if (a == 1) { c.bias = nb + (node * 4) * ISIZE; c.outf = g_t0; }
            else { c.outf = g_t0; }
            return true;
        }
        if (z == 1) {
            if (a != 0 && a != 1 && a != 3 && a != 5) return false;
            c.A = g_k; c.wb = nwb0 + WELEM;
            if (a == 0) { c.bias = nb + (node * 4 + 1) * ISIZE; c.outh = g_Kh; c.outl = g_Kl; }
            else if (a == 1) { c.bias = nb + (node * 4 + 1) * ISIZE; c.outf = g_t1; }
            else if (a == 3) { c.outf = g_t1; }
            else { c.bias = nb + (node * 4 + 1) * ISIZE; c.actc = 2; c.outf = g_t1; }
            return true;
        }
        if (a != 0 && a != 3) return false;
        c.A = g_v; c.wb = nwb0 + 2 * WELEM;
        if (a == 0) { c.bias = nb + (node * 4 + 2) * ISIZE; c.outh = g_Vh; c.outl = g_Vl; }
        else { c.outf = g_t2; }
        return true;
    }
    if (a != 0 && a != 1 && a != 3) return false;
    c.wb = nwb0 + 3 * WELEM; c.bias = nb + (node * 4 + 3) * ISIZE;
    c.res = g_q; c.scale = r.aw; c.outf = g_outs[node];
    if (a == 0) c.A = g_t3;
    else if (a == 1) c.comb = 1;
    else c.comb = 2;
    return true;
}

// ---------------------------------------------------------------- fused LN/split tensor-core GEMM
// C[4096,512] = act(A)[4096,512] * W[512,512]; BM=64 BN=128 BK=64.
// Per k-chunk loads Ah,Al (built on the fly from fp32 A) and Bh,Bl; 3 mma passes.
__global__ void __launch_bounds__(256) mma_gemm(int node, int set,
        const float* ie, const float* io,
        const float* eb, const float* eg, const float* ebe,
        const float* nb, const float* ng, const float* nbe) {
    int z = blockIdx.z;
    Cfg c;
    if (!resolve2(node, set, z, ie, io, eb, eg, ebe, nb, ng, nbe, c)) return;

    int tid = threadIdx.x;
    int m0 = blockIdx.y * 64, n0 = blockIdx.x * 128;

    if (c.copy) {
        for (int idx = tid; idx < 64 * 128; idx += 256) {
            int rr = idx >> 7, cc = idx & 127;
            size_t i = (size_t)(m0 + rr) * ISIZE + n0 + cc;
            c.outf[i] = c.scale * c.A[i];
        }
        return;
    }

    extern __shared__ char dynsmem[];
    unsigned sb = (unsigned)__cvta_generic_to_shared(dynsmem);
    // stage layout: [Ah 8K][Al 8K][Bh 16K][Bl 16K] = 48K; two stages
    __shared__ float s_mean[64], s_rstd[64];

    int lane = tid & 31, warp = tid >> 5;
    int wm = warp >> 2, wn = warp & 3;

    // LN stats pre-pass (4 threads per row)
    if (c.use_ln) {
        int row = tid >> 2, part = tid & 3;
        const float4* p = (const float4*)(c.A + (size_t)(m0 + row) * ISIZE + part * 128);
        float s = 0.f, s2 = 0.f;
        #pragma unroll 8
        for (int i = 0; i < 32; i++) {
            float4 v = p[i];
            s += v.x + v.y + v.z + v.w;
            s2 += v.x * v.x + v.y * v.y + v.z * v.z + v.w * v.w;
        }
        s  += __shfl_xor_sync(0xffffffffu, s, 1);
        s2 += __shfl_xor_sync(0xffffffffu, s2, 1);
        s  += __shfl_xor_sync(0xffffffffu, s, 2);
        s2 += __shfl_xor_sync(0xffffffffu, s2, 2);
        if (part == 0) {
            float mn = s * (1.f / ISIZE);
            float var = s2 * (1.f / ISIZE) - mn * mn;
            if (var < 0.f) var = 0.f;
            s_mean[row] = mn;
            s_rstd[row] = rsqrtf(var + EPSF);
        }
        __syncthreads();
    }

    const __half* Wh = g_Wh + c.wb;
    const __half* Wl = g_Wl + c.wb;

    auto fillA = [&](int it, int buf) {
        int kk = it * 64;
        char* sbase = dynsmem + buf * 49152;
        int row = tid >> 2, part = tid & 3;     // 16 cols per thread
        size_t base = (size_t)(m0 + row) * ISIZE + kk + part * 16;
        float x[16];
        if (c.comb == 1) {
            const float4* p0 = (const float4*)(g_t0 + base);
            const float4* p1 = (const float4*)(g_t1 + base);
            #pragma unroll
            for (int u = 0; u < 4; u++) {
                float4 a = p0[u], b = p1[u];
                x[u*4+0] = gelu_f(a.x) * b.x; x[u*4+1] = gelu_f(a.y) * b.y;
                x[u*4+2] = gelu_f(a.z) * b.z; x[u*4+3] = gelu_f(a.w) * b.w;
            }
        } else if (c.comb == 2) {
            const float4* p0 = (const float4*)(g_t0 + base);
            const float4* p1 = (const float4*)(g_t1 + base);
            const float4* p2 = (const float4*)(g_t2 + base);
            #pragma unroll
            for (int u = 0; u < 4; u++) {
                float4 a = p0[u], b = p1[u], d = p2[u];
                x[u*4+0] = fmaxf(a.x + b.x + d.x, 0.f); x[u*4+1] = fmaxf(a.y + b.y + d.y, 0.f);
                x[u*4+2] = fmaxf(a.z + b.z + d.z, 0.f); x[u*4+3] = fmaxf(a.w + b.w + d.w, 0.f);
            }
        } else {
            const float4* p = (const float4*)(c.A + base);
            #pragma unroll
            for (int u = 0; u < 4; u++) {
                float4 v = p[u];
                x[u*4+0] = v.x; x[u*4+1] = v.y; x[u*4+2] = v.z; x[u*4+3] = v.w;
            }
            if (c.use_ln) {
                float mn = s_mean[row], rs = s_rstd[row];
                #pragma unroll
                for (int j = 0; j < 16; j++) {
                    int col = kk + part * 16 + j;
                    x[j] = (x[j] - mn) * rs * c.g[col] + c.be[col];
                }
            }
        }
        #pragma unroll
        for (int cch = 0; cch < 2; cch++) {
            int ch = part * 2 + cch;
            unsigned off = (unsigned)((row * 8 + (ch ^ (row & 7))) * 16);
            __half h8[8], l8[8];
            #pragma unroll
            for (int j = 0; j < 8; j++) {
                float v = x[cch * 8 + j];
                __half hh = __float2half_rn(v);
                h8[j] = hh;
                l8[j] = __float2half_rn(v - __half2float(hh));
            }
            *(uint4*)(sbase + off) = *(const uint4*)h8;
            *(uint4*)(sbase + 8192 + off) = *(const uint4*)l8;
        }
    };

    auto loadB = [&](int it, int buf) {
        int kk = it * 64;
        unsigned db = sb + buf * 49152 + 16384;
        #pragma unroll
        for (int j = 0; j < 4; j++) {
            int id = tid + j * 256;
            int row = id >> 4, ch = id & 15;
            unsigned off = (unsigned)((row * 16 + (ch ^ (row & 7))) * 16);
            size_t gidx = (size_t)(kk + row) * ISIZE + n0 + ch * 8;
            cp_async16(db + off, Wh + gidx);
            cp_async16(db + 16384 + off, Wl + gidx);
        }
        cp_commit();
    };

    float acc[2][4][4];
    #pragma unroll
    for (int mt = 0; mt < 2; mt++)
        #pragma unroll
        for (int nt = 0; nt < 4; nt++)
            #pragma unroll
            for (int r = 0; r < 4; r++) acc[mt][nt][r] = 0.f;

    auto compute = [&](int buf) {
        unsigned baA = sb + buf * 49152;
        unsigned baB = sb + buf * 49152 + 16384;
        #pragma unroll
        for (int s = 0; s < 4; s++) {
            unsigned aH[2][4], aL[2][4];
            #pragma unroll
            for (int mt = 0; mt < 2; mt++) {
                int r = wm * 32 + mt * 16 + (lane & 15);
                int ch = s * 2 + (lane >> 4);
                unsigned off = (unsigned)((r * 8 + (ch ^ (r & 7))) * 16);
                ldmx4(aH[mt], baA + off);
                ldmx4(aL[mt], baA + 8192 + off);
            }
            unsigned bH[4][2], bL[4][2];
            #pragma unroll
            for (int nt2 = 0; nt2 < 2; nt2++) {
                int k = s * 16 + (lane & 15);
                int ch = wn * 4 + nt2 * 2 + (lane >> 4);
                unsigned off = (unsigned)((k * 16 + (ch ^ (k & 7))) * 16);
                unsigned tmp[4];
                ldmx4t(tmp, baB + off);
                bH[nt2 * 2][0] = tmp[0]; bH[nt2 * 2][1] = tmp[1];
                bH[nt2 * 2 + 1][0] = tmp[2]; bH[nt2 * 2 + 1][1] = tmp[3];
                ldmx4t(tmp, baB + 16384 + off);
                bL[nt2 * 2][0] = tmp[0]; bL[nt2 * 2][1] = tmp[1];
                bL[nt2 * 2 + 1][0] = tmp[2]; bL[nt2 * 2 + 1][1] = tmp[3];
            }
            #pragma unroll
            for (int mt = 0; mt < 2; mt++)
                #pragma unroll
                for (int nt = 0; nt < 4; nt++) {
                    mma16816(acc[mt][nt], aH[mt], bH[nt]);
                    mma16816(acc[mt][nt], aL[mt], bH[nt]);
                    mma16816(acc[mt][nt], aH[mt], bL[nt]);
                }
        }
    };

    fillA(0, 0);
    loadB(0, 0);
    #pragma unroll 1
    for (int it = 0; it < 8; it++) {
        int buf = it & 1;
        if (it < 7) {
            loadB(it + 1, buf ^ 1);
            fillA(it + 1, buf ^ 1);
            cp_wait<1>();
        } else {
            cp_wait<0>();
        }
        __syncthreads();
        compute(buf);
        __syncthreads();
    }

    #pragma unroll
    for (int mt = 0; mt < 2; mt++) {
        #pragma unroll
        for (int nt = 0; nt < 4; nt++) {
            #pragma unroll
            for (int r = 0; r < 4; r++) {
                int m = m0 + wm * 32 + mt * 16 + (lane >> 2) + ((r & 2) ? 8 : 0);
                int n = n0 + wn * 32 + nt * 8 + (lane & 3) * 2 + (r & 1);
                size_t idx = (size_t)m * ISIZE + n;
                float v = acc[mt][nt][r];
                if (c.bias) v += c.bias[n];
                if (c.actc == 1) v = fmaxf(v, 0.f);
                else if (c.actc == 2) v = gelu_f(v);
                if (c.outh) {
                    __half h = __float2half_rn(v);
                    c.outh[idx] = h;
                    c.outl[idx] = __float2half_rn(v - __half2float(h));
                } else {
                    if (c.res) v += c.res[idx];
                    c.outf[idx] = v * c.scale;
                }
            }
        }
    }
}

// ---------------------------------------------------------------- attention: scores (mma fp16x3)
__global__ void __launch_bounds__(256) attn_scores_mma(int node,
        const unsigned char* __restrict__ srcm, const unsigned char* __restrict__ tgtm) {
    const Route r = g_route[node];
    if (r.act != 0) return;
    int bh = blockIdx.z, b = bh >> 3, h = bh & 7;
    int q0 = blockIdx.y * 64, k0 = blockIdx.x * 128;

    __shared__ __half sQ[2][64 * 64];
    __shared__ __half sK[2][128 * 64];
    unsigned sq0 = (unsigned)__cvta_generic_to_shared(&sQ[0][0]);
    unsigned sk0 = (unsigned)__cvta_generic_to_shared(&sK[0][0]);

    int tid = threadIdx.x, lane = tid & 31, warp = tid >> 5;
    int wm = warp >> 2, wn = warp & 3;

    const __half* gq[2] = { g_Qh, g_Ql };
    const __half* gk[2] = { g_Kh, g_Kl };
    #pragma unroll
    for (int sp = 0; sp < 2; sp++) {
        #pragma unroll
        for (int j = 0; j < 2; j++) {
            int id = tid + j * 256;
            int row = id >> 3, ch = id & 7;
            const void* g = gq[sp] + (size_t)(b * SLEN + q0 + row) * ISIZE + h * 64 + ch * 8;
            cp_async16(sq0 + sp * 8192 + (unsigned)((row * 8 + (ch ^ (row & 7))) * 16), g);
        }
        #pragma unroll
        for (int j = 0; j < 4; j++) {
            int id = tid + j * 256;
            int row = id >> 3, ch = id & 7;
            const void* g = gk[sp] + (size_t)(b * SLEN + k0 + row) * ISIZE + h * 64 + ch * 8;
            cp_async16(sk0 + sp * 16384 + (unsigned)((row * 8 + (ch ^ (row & 7))) * 16), g);
        }
    }
    cp_commit(); cp_wait<0>();
    __syncthreads();

    float acc[2][4][4];
    #pragma unroll
    for (int mt = 0; mt < 2; mt++)
        #pragma unroll
        for (int nt = 0; nt < 4; nt++)
            #pragma unroll
            for (int rr = 0; rr < 4; rr++) acc[mt][nt][rr] = 0.f;

    #pragma unroll
    for (int ph = 0; ph < 3; ph++) {
        unsigned baQ = sq0 + ((ph == 1) ? 8192 : 0);
        unsigned baK = sk0 + ((ph == 2) ? 16384 : 0);
        #pragma unroll
        for (int s = 0; s < 4; s++) {
            unsigned af[2][4];
            #pragma unroll
            for (int mt = 0; mt < 2; mt++) {
                int rr = wm * 32 + mt * 16 + (lane & 15);
                int ch = s * 2 + (lane >> 4);
                ldmx4(af[mt], baQ + (unsigned)((rr * 8 + (ch ^ (rr & 7))) * 16));
            }
            unsigned bf[4][2];
            #pragma unroll
            for (int ng2 = 0; ng2 < 2; ng2++) {
                int nrow = wn * 32 + ng2 * 16 + (lane & 7) + ((lane >> 4) ? 8 : 0);
                int ch = s * 2 + ((lane >> 3) & 1);
                unsigned tmp[4];
                ldmx4(tmp, baK + (unsigned)((nrow * 8 + (ch ^ (nrow & 7))) * 16));
                bf[ng2 * 2][0] = tmp[0]; bf[ng2 * 2][1] = tmp[1];
                bf[ng2 * 2 + 1][0] = tmp[2]; bf[ng2 * 2 + 1][1] = tmp[3];
            }
            #pragma unroll
            for (int mt = 0; mt < 2; mt++)
                #pragma unroll
                for (int nt = 0; nt < 4; nt++)
                    mma16816(acc[mt][nt], af[mt], bf[nt]);
        }
    }

    const unsigned char* msk = (r.ktype == -1) ? tgtm : srcm;
    #pragma unroll
    for (int mt = 0; mt < 2; mt++) {
        #pragma unroll
        for (int nt = 0; nt < 4; nt++) {
            #pragma unroll
            for (int rr = 0; rr < 4; rr++) {
                int m = q0 + wm * 32 + mt * 16 + (lane >> 2) + ((rr & 2) ? 8 : 0);
                int n = k0 + wn * 32 + nt * 8 + (lane & 3) * 2 + (rr & 1);
                float s = acc[mt][nt][rr] * 0.125f;
                if (msk[b * SLEN + n]) s = -1e9f;
                g_scores[((size_t)bh << 20) + (size_t)m * SLEN + n] = s;
            }
        }
    }
}

// ---------------------------------------------------------------- softmax -> Ph/Pl
__global__ void __launch_bounds__(256) attn_softmax(int node) {
    if (g_route[node].act != 0) return;
    __shared__ float red[8];
    for (int row = blockIdx.x; row < BB * NHEAD * SLEN; row += gridDim.x) {
        const float* p = g_scores + (size_t)row * SLEN;
        float v[4];
        float mx = -1e30f;
        #pragma unroll
        for (int t = 0; t < 4; t++) {
            v[t] = p[threadIdx.x + t * 256];
            mx = fmaxf(mx, v[t]);
        }
        for (int o = 16; o; o >>= 1) mx = fmaxf(mx, __shfl_down_sync(0xffffffffu, mx, o));
        if ((threadIdx.x & 31) == 0) red[threadIdx.x >> 5] = mx;
        __syncthreads();
        float MX = red[0];
        #pragma unroll
        for (int w = 1; w < 8; w++) MX = fmaxf(MX, red[w]);
        __syncthreads();
        float s = 0.f;
        #pragma unroll
        for (int t = 0; t < 4; t++) { v[t] = expf(v[t] - MX); s += v[t]; }
        for (int o = 16; o; o >>= 1) s += __shfl_down_sync(0xffffffffu, s, o);
        if ((threadIdx.x & 31) == 0) red[threadIdx.x >> 5] = s;
        __syncthreads();
        float S = 0.f;
        #pragma unroll
        for (int w = 0; w < 8; w++) S += red[w];
        float inv = 1.f / S;
        #pragma unroll
        for (int t = 0; t < 4; t++) {
            float val = v[t] * inv;
            size_t idx = (size_t)row * SLEN + threadIdx.x + t * 256;
            __half hh = __float2half_rn(val);
            g_Ph[idx] = hh;
            g_Pl[idx] = __float2half_rn(val - __half2float(hh));
        }
        __syncthreads();
    }
}

// ---------------------------------------------------------------- attention: PV (mma fp16x3)
__global__ void __launch_bounds__(256) attn_pv_mma(int node) {
    const Route r = g_route[node];
    if (r.act != 0) return;
    int bh = blockIdx.y, b = bh >> 3, h = bh & 7;
    int q0 = blockIdx.x * 64;

    __shared__ __half sP[2][64 * 64];
    __shared__ __half sV[2][64 * 64];
    unsigned sp0 = (unsigned)__cvta_generic_to_shared(&sP[0][0]);
    unsigned sv0 = (unsigned)__cvta_generic_to_shared(&sV[0][0]);

    int tid = threadIdx.x, lane = tid & 31, warp = tid >> 5;
    int wm = warp >> 1, wn = warp & 1;

    const __half* gp[2] = { g_Ph + ((size_t)bh << 20), g_Pl + ((size_t)bh << 20) };
    const __half* gv[2] = { g_Vh, g_Vl };

    float acc[4][4];
    #pragma unroll
    for (int nt = 0; nt < 4; nt++)
        #pragma unroll
        for (int rr = 0; rr < 4; rr++) acc[nt][rr] = 0.f;

    for (int kt = 0; kt < 16; kt++) {
        #pragma unroll
        for (int sp = 0; sp < 2; sp++) {
            #pragma unroll
            for (int j = 0; j < 2; j++) {
                int id = tid + j * 256;
                int row = id >> 3, ch = id & 7;
                const void* g = gp[sp] + (size_t)(q0 + row) * SLEN + kt * 64 + ch * 8;
                cp_async16(sp0 + sp * 8192 + (unsigned)((row * 8 + (ch ^ (row & 7))) * 16), g);
            }
            #pragma unroll
            for (int j = 0; j < 2; j++) {
                int id = tid + j * 256;
                int row = id >> 3, ch = id & 7;
                const void* g = gv[sp] + (size_t)(b * SLEN + kt * 64 + row) * ISIZE + h * 64 + ch * 8;
                cp_async16(sv0 + sp * 8192 + (unsigned)((row * 8 + (ch ^ (row & 7))) * 16), g);
            }
        }
        cp_commit(); cp_wait<0>();
        __syncthreads();

        #pragma unroll
        for (int s = 0; s < 4; s++) {
            unsigned aH[4], aL[4];
            {
                int rr = wm * 16 + (lane & 15);
                int ch = s * 2 + (lane >> 4);
                unsigned off = (unsigned)((rr * 8 + (ch ^ (rr & 7))) * 16);
                ldmx4(aH, sp0 + off);
                ldmx4(aL, sp0 + 8192 + off);
            }
            unsigned bH[4][2], bL[4][2];
            #pragma unroll
            for (int nt2 = 0; nt2 < 2; nt2++) {
                int k = s * 16 + (lane & 15);
                int ch = wn * 4 + nt2 * 2 + (lane >> 4);
                unsigned off = (unsigned)((k * 8 + (ch ^ (k & 7))) * 16);
                unsigned tmp[4];
                ldmx4t(tmp, sv0 + off);
                bH[nt2 * 2][0] = tmp[0]; bH[nt2 * 2][1] = tmp[1];
                bH[nt2 * 2 + 1][0] = tmp[2]; bH[nt2 * 2 + 1][1] = tmp[3];
                ldmx4t(tmp, sv0 + 8192 + off);
                bL[nt2 * 2][0] = tmp[0]; bL[nt2 * 2][1] = tmp[1];
                bL[nt2 * 2 + 1][0] = tmp[2]; bL[nt2 * 2 + 1][1] = tmp[3];
            }
            #pragma unroll
            for (int nt = 0; nt < 4; nt++) {
                mma16816(acc[nt], aH, bH[nt]);
                mma16816(acc[nt], aL, bH[nt]);
                mma16816(acc[nt], aH, bL[nt]);
            }
        }
        __syncthreads();
    }

    #pragma unroll
    for (int nt = 0; nt < 4; nt++) {
        #pragma unroll
        for (int rr = 0; rr < 4; rr++) {
            int m = q0 + wm * 16 + (lane >> 2) + ((rr & 2) ? 8 : 0);
            int n = wn * 32 + nt * 8 + (lane & 3) * 2 + (rr & 1);
            g_t3[(size_t)(b * SLEN + m) * ISIZE + h * 64 + n] = acc[nt][rr];
        }
    }
}

// ---------------------------------------------------------------- elementwise final (acts 2,4,5,6,7)
__global__ void ew_final(int node, const float* ng, const float* nbe) {
    const Route r = g_route[node];
    int a = r.act;
    if (a == 0 || a == 1 || a == 3) return;
    int row = blockIdx.x;
    size_t base = (size_t)row * ISIZE;
    float* out = g_outs[node];
    if (a == 4 || a == 5 || a == 6) {
        for (int i = threadIdx.x; i < ISIZE; i += 128) {
            size_t idx = base + i;
            float q = g_q[idx];
            float v;
            if (a == 4) v = q * (1.f / (1.f + expf(-g_k[idx]))) + g_v[idx];
            else if (a == 5) v = q + g_t1[idx];
            else v = q + g_k[idx];
            out[idx] = r.aw * v;
        }
        return;
    }
    float vals[4];
    float s = 0.f, s2 = 0.f;
    #pragma unroll
    for (int t = 0; t < 4; t++) {
        int i = threadIdx.x + t * 128;
        size_t idx = base + i;
        float x = (a == 2) ? (g_q[idx] + g_k[idx] + g_v[idx]) : g_q[idx];
        vals[t] = x; s += x; s2 += x * x;
    }
    for (int o = 16; o; o >>= 1) {
        s += __shfl_down_sync(0xffffffffu, s, o);
        s2 += __shfl_down_sync(0xffffffffu, s2, o);
    }
    __shared__ float ra[4], rb[4];
    if ((threadIdx.x & 31) == 0) { ra[threadIdx.x >> 5] = s; rb[threadIdx.x >> 5] = s2; }
    __syncthreads();
    float S = ra[0] + ra[1] + ra[2] + ra[3];
    float S2 = rb[0] + rb[1] + rb[2] + rb[3];
    float m = S * (1.f / ISIZE);
    float var = S2 * (1.f / ISIZE) - m * m;
    if (var < 0.f) var = 0.f;
    float rs = rsqrtf(var + EPSF);
    #pragma unroll
    for (int t = 0; t < 4; t++) {
        int i = threadIdx.x + t * 128;
        out[base + i] = r.aw * ((vals[t] - m) * rs * ng[node * ISIZE + i] + nbe[node * ISIZE + i]);
    }
}

// ---------------------------------------------------------------- final sum + LN
__global__ void final_kernel(const float* og, const float* obe, float* out) {
    int row = blockIdx.x;
    size_t base = (size_t)row * ISIZE;
    float vals[4];
    float s = 0.f, s2 = 0.f;
    #pragma unroll
    for (int t = 0; t < 4; t++) {
        int i = threadIdx.x + t * 128;
        float x = 0.f;
        for (int n = 0; n < NNOD; n++)
            if (!g_proc[n]) x += g_outs[n][base + i];
        vals[t] = x; s += x; s2 += x * x;
    }
    for (int o = 16; o; o >>= 1) {
        s += __shfl_down_sync(0xffffffffu, s, o);
        s2 += __shfl_down_sync(0xffffffffu, s2, o);
    }
    __shared__ float ra[4], rb[4];
    if ((threadIdx.x & 31) == 0) { ra[threadIdx.x >> 5] = s; rb[threadIdx.x >> 5] = s2; }
    __syncthreads();
    float S = ra[0] + ra[1] + ra[2] + ra[3];
    float S2 = rb[0] + rb[1] + rb[2] + rb[3];
    float m = S * (1.f / ISIZE);
    float var = S2 * (1.f / ISIZE) - m * m;
    if (var < 0.f) var = 0.f;
    float rs = rsqrtf(var + EPSF);
    #pragma unroll
    for (int t = 0; t < 4; t++) {
        int i = threadIdx.x + t * 128;
        out[base + i] = (vals[t] - m) * rs * og[i] + obe[i];
    }
}

// ---------------------------------------------------------------- launch
extern "C" void kernel_launch(void* const* d_in, const int* in_sizes, int n_in,
                              void* d_out, int out_size) {
    const float* ie  = (const float*)d_in[0];
    const float* io  = (const float*)d_in[1];
    const float* npw = (const float*)d_in[2];
    const float* epw = (const float*)d_in[3];
    const float* eW  = (const float*)d_in[4];
    const float* eb  = (const float*)d_in[5];
    const float* eg  = (const float*)d_in[6];
    const float* ebe = (const float*)d_in[7];
    const float* nW  = (const float*)d_in[8];
    const float* nb  = (const float*)d_in[9];
    const float* ng  = (const float*)d_in[10];
    const float* nbe = (const float*)d_in[11];
    const float* og  = (const float*)d_in[12];
    const float* obe = (const float*)d_in[13];
    const unsigned char* srcm = (const unsigned char*)d_in[14];
    const unsigned char* tgtm = (const unsigned char*)d_in[15];
    float* out = (float*)d_out;

    cudaFuncSetAttribute(mma_gemm, cudaFuncAttributeMaxDynamicSharedMemorySize, GEMM_SMEM);

    route_kernel<<<1, 32>>>(npw, epw);
    wsplit_kernel<<<dim3(64, NMAT), 256>>>(eW, nW);

    dim3 gg3(ISIZE / 128, NROWS / 64, 3);
    dim3 gg1(ISIZE / 128, NROWS / 64, 1);
    for (int c = 0; c < NNOD; c++) {
        mma_gemm<<<gg3, 256, GEMM_SMEM>>>(c, 0, ie, io, eb, eg, ebe, nb, ng, nbe);
        mma_gemm<<<gg3, 256, GEMM_SMEM>>>(c, 1, ie, io, eb, eg, ebe, nb, ng, nbe);
        attn_scores_mma<<<dim3(8, 16, 32), 256>>>(c, srcm, tgtm);
        attn_softmax<<<4096, 256>>>(c);
        attn_pv_mma<<<dim3(16, 32), 256>>>(c);
        mma_gemm<<<gg1, 256, GEMM_SMEM>>>(c, 2, ie, io, eb, eg, ebe, nb, ng, nbe);
        ew_final<<<NROWS, 128>>>(c, ng, nbe);
    }
    final_kernel<<<NROWS, 128>>>(og, obe, out);
}

// round 7
// speedup vs baseline: 1.1717x; 1.1717x over previous
#include <cuda_runtime.h>
#include <cuda_fp16.h>
#include <math.h>

#define NNOD 8
#define NEDGE 34
#define ISIZE 512
#define NHEAD 8
#define BB 4
#define SLEN 1024
#define NROWS (BB*SLEN)
#define BSD (NROWS*ISIZE)
#define EPSF 1e-6f
#define WELEM (ISIZE*ISIZE)
#define NMAT (NEDGE + NNOD*4)
#define NW_TOT (NMAT * WELEM)
#define SCORE_N (BB*NHEAD*SLEN*SLEN)
#define GEMM_SMEM 98304

struct Route {
    int act, lind, snode, nsrc;
    int qsel, ksel, vsel;
    int q_in, q_e, q_op;
    int k_in, k_e, k_op;
    int v_in, v_e, v_op;
    int ktype;
    float aw, qw, kw, vw;
};

__device__ Route g_route[NNOD];
__device__ int   g_proc[NNOD];
__device__ int   g_wneed[NMAT];

__device__ float g_outs[NNOD][BSD];
__device__ float g_q[BSD], g_k[BSD], g_v[BSD];
__device__ float g_t0[BSD], g_t1[BSD], g_t2[BSD], g_t3[BSD];
__device__ float g_scores[SCORE_N];
__device__ __half g_xh[3][BSD], g_xl[3][BSD];
__device__ __half g_Qh[BSD], g_Ql[BSD], g_Kh[BSD], g_Kl[BSD], g_Vh[BSD], g_Vl[BSD];
__device__ __half g_Ph[SCORE_N], g_Pl[SCORE_N];
__device__ __half g_Wh[NW_TOT], g_Wl[NW_TOT];

// ---------------------------------------------------------------- helpers
__device__ __forceinline__ float gelu_f(float x) {
    const float c0 = 0.7978845608028654f, c1 = 0.044715f;
    float x3 = x * x * x;
    return 0.5f * x * (1.f + tanhf(c0 * (x + c1 * x3)));
}
__device__ __forceinline__ const float* sel_in(int inn, const float* ie, const float* io) {
    if (inn == -2) return ie;
    if (inn == -1) return io;
    return g_outs[inn];
}
__device__ __forceinline__ void cp_async16(unsigned saddr, const void* gptr) {
    asm volatile("cp.async.cg.shared.global [%0], [%1], 16;\n" :: "r"(saddr), "l"(gptr));
}
template<int N> __device__ __forceinline__ void cp_wait() {
    asm volatile("cp.async.wait_group %0;\n" :: "n"(N));
}
__device__ __forceinline__ void cp_commit() {
    asm volatile("cp.async.commit_group;\n");
}
__device__ __forceinline__ void ldmx4(unsigned* r, unsigned addr) {
    asm volatile("ldmatrix.sync.aligned.m8n8.x4.shared.b16 {%0,%1,%2,%3}, [%4];\n"
        : "=r"(r[0]), "=r"(r[1]), "=r"(r[2]), "=r"(r[3]) : "r"(addr));
}
__device__ __forceinline__ void ldmx4t(unsigned* r, unsigned addr) {
    asm volatile("ldmatrix.sync.aligned.m8n8.x4.trans.shared.b16 {%0,%1,%2,%3}, [%4];\n"
        : "=r"(r[0]), "=r"(r[1]), "=r"(r[2]), "=r"(r[3]) : "r"(addr));
}
__device__ __forceinline__ void mma16816(float* c, const unsigned* a, const unsigned* b) {
    asm volatile(
        "mma.sync.aligned.m16n8k16.row.col.f32.f16.f16.f32 "
        "{%0,%1,%2,%3}, {%4,%5,%6,%7}, {%8,%9}, {%0,%1,%2,%3};\n"
        : "+f"(c[0]), "+f"(c[1]), "+f"(c[2]), "+f"(c[3])
        : "r"(a[0]), "r"(a[1]), "r"(a[2]), "r"(a[3]), "r"(b[0]), "r"(b[1]));
}

// ---------------------------------------------------------------- routing
__global__ void route_kernel(const float* __restrict__ node_p,
                             const float* __restrict__ edge_p) {
    if (threadIdx.x != 0 || blockIdx.x != 0) return;
    for (int i = 0; i < NNOD; i++) g_proc[i] = 0;
    for (int i = 0; i < NMAT; i++) g_wneed[i] = 0;
    int lind = 0;
    for (int c = 0; c < NNOD; c++) {
        Route r;
        r.lind = lind;
        int nsrc = (c + 2 < 5) ? c + 2 : 5;
        r.nsrc = nsrc;
        int snode = c - nsrc;
        r.snode = snode;
        int nL = nsrc * 5;

        const float* np = node_p + c * 8;
        int act = 0;
        for (int j = 1; j < 8; j++) if (np[j] > np[act]) act = j;
        float mx = np[0];
        for (int j = 1; j < 8; j++) mx = fmaxf(mx, np[j]);
        float ssum = 0.f;
        for (int j = 0; j < 8; j++) ssum += expf(np[j] - mx);
        r.act = act;
        r.aw = expf(np[act] - mx) / ssum;

        const float* epq = edge_p + 0 * NEDGE * 5 + lind * 5;
        const float* epk = edge_p + 1 * NEDGE * 5 + lind * 5;
        const float* epv = edge_p + 2 * NEDGE * 5 + lind * 5;

        int qsel = 5;
        for (int j = 6; j < nL; j++) if (epq[j] > epq[qsel]) qsel = j;
        {
            float m2 = epq[5];
            for (int j = 6; j < nL; j++) m2 = fmaxf(m2, epq[j]);
            float ss = 0.f;
            for (int j = 5; j < nL; j++) ss += expf(epq[j] - m2);
            r.qw = expf(epq[qsel] - m2) / ss;
        }
        r.qsel = qsel;
        r.ksel = -1; r.vsel = -1; r.kw = 0.f; r.vw = 0.f; r.ktype = 0;
        r.k_in = 0; r.k_e = 0; r.k_op = 0; r.v_in = 0; r.v_e = 0; r.v_op = 0;

        int use_km = (act > 0);
        if (act < 7) {
            int st = use_km ? 5 : 0;
            int ks = st;
            for (int j = st + 1; j < nL; j++) if (epk[j] > epk[ks]) ks = j;
            float m2 = epk[st];
            for (int j = st + 1; j < nL; j++) m2 = fmaxf(m2, epk[j]);
            float ss = 0.f;
            for (int j = st; j < nL; j++) ss += expf(epk[j] - m2);
            r.ksel = ks;
            r.kw = expf(epk[ks] - m2) / ss;
            r.ktype = (ks / 5 == 0) ? -2 : -1;
            if (act < 5) {
                if (act == 0 && r.ktype == -2) {
                    int vs = 0;
                    for (int j = 1; j < 5; j++) if (epv[j] > epv[vs]) vs = j;
                    float m3 = epv[0];
                    for (int j = 1; j < 5; j++) m3 = fmaxf(m3, epv[j]);
                    float s3 = 0.f;
                    for (int j = 0; j < 5; j++) s3 += expf(epv[j] - m3);
                    r.vsel = vs;
                    r.vw = expf(epv[vs] - m3) / s3;
                } else {
                    int vs = st;
                    for (int j = st + 1; j < nL; j++) if (epv[j] > epv[vs]) vs = j;
                    float m3 = epv[st];
                    for (int j = st + 1; j < nL; j++) m3 = fmaxf(m3, epv[j]);
                    float s3 = 0.f;
                    for (int j = st; j < nL; j++) s3 += expf(epv[j] - m3);
                    r.vsel = vs;
                    r.vw = expf(epv[vs] - m3) / s3;
                }
            }
        }
        int se = qsel / 5;
        r.q_op = qsel % 5; r.q_e = lind + se;
        r.q_in = (se == 0) ? -2 : snode + se;
        if (r.q_in >= 0) g_proc[r.q_in] = 1;
        if (r.q_op < 4) g_wneed[r.q_e] = 1;
        if (r.ksel >= 0) {
            se = r.ksel / 5; r.k_op = r.ksel % 5; r.k_e = lind + se;
            r.k_in = (se == 0) ? -2 : snode + se;
            if (r.k_in >= 0) g_proc[r.k_in] = 1;
            if (r.k_op < 4) g_wneed[r.k_e] = 1;
        }
        if (r.vsel >= 0) {
            se = r.vsel / 5; r.v_op = r.vsel % 5; r.v_e = lind + se;
            r.v_in = (se == 0) ? -2 : snode + se;
            if (r.v_in >= 0) g_proc[r.v_in] = 1;
            if (r.v_op < 4) g_wneed[r.v_e] = 1;
        }
        int nb0 = NEDGE + c * 4;
        if (act == 0) { g_wneed[nb0]=1; g_wneed[nb0+1]=1; g_wneed[nb0+2]=1; g_wneed[nb0+3]=1; }
        else if (act == 1) { g_wneed[nb0]=1; g_wneed[nb0+1]=1; g_wneed[nb0+3]=1; }
        else if (act == 3) { g_wneed[nb0]=1; g_wneed[nb0+1]=1; g_wneed[nb0+2]=1; g_wneed[nb0+3]=1; }
        else if (act == 5) { g_wneed[nb0+1]=1; }
        g_route[c] = r;
        lind += nsrc;
    }
}

// ---------------------------------------------------------------- gated weight split
__global__ void wsplit_kernel(const float* __restrict__ eW, const float* __restrict__ nW) {
    int m = blockIdx.y;
    if (!g_wneed[m]) return;
    size_t base = (size_t)m * WELEM;
    const float* src = (m < NEDGE) ? (eW + base) : (nW + base - (size_t)NEDGE * WELEM);
    for (int i = blockIdx.x * blockDim.x + threadIdx.x; i < WELEM; i += gridDim.x * blockDim.x) {
        float v = src[i];
        __half h = __float2half_rn(v);
        g_Wh[base + i] = h;
        g_Wl[base + i] = __float2half_rn(v - __half2float(h));
    }
}

// ---------------------------------------------------------------- stage resolve
struct Cfg {
    const float* A;
    float* outf; __half* outh; __half* outl;
    const float* bias; const float* res; const float* g; const float* be;
    size_t wb; float scale;
    int use_ln, actc, copy, comb;
};

__device__ bool resolve2(int node, int set, int z,
    const float* ie, const float* io,
    const float* eb, const float* eg, const float* ebe,
    const float* nb, const float* ng, const float* nbe, Cfg& c) {
    const Route r = g_route[node];
    c.A = nullptr; c.outf = nullptr; c.outh = nullptr; c.outl = nullptr;
    c.bias = nullptr; c.res = nullptr; c.g = nullptr; c.be = nullptr;
    c.wb = 0; c.scale = 1.f; c.use_ln = 0; c.actc = 0; c.copy = 0; c.comb = 0;
    if (set == 0) {
        int sel, e, op, inn; float w; float* out;
        if (z == 0) { sel = r.qsel; e = r.q_e; op = r.q_op; inn = r.q_in; w = r.qw; out = g_q; }
        else if (z == 1) { sel = r.ksel; e = r.k_e; op = r.k_op; inn = r.k_in; w = r.kw; out = g_k; }
        else { sel = r.vsel; e = r.v_e; op = r.v_op; inn = r.v_in; w = r.vw; out = g_v; }
        if (sel < 0) return false;
        c.A = sel_in(inn, ie, io); c.outf = out; c.scale = w;
        if (op == 4) { c.copy = 1; return true; }
        c.wb = (size_t)e * WELEM;
        c.bias = eb + e * ISIZE;
        if (op < 3) {
            c.use_ln = 1; c.g = eg + e * ISIZE; c.be = ebe + e * ISIZE;
            c.actc = (op == 0) ? 1 : (op == 1) ? 2 : 0;
        }
        return true;
    }
    int a = r.act;
    size_t nwb0 = (size_t)(NEDGE + node * 4) * WELEM;
    if (set == 1) {
        if (z == 0) {
            if (a != 0 && a != 1 && a != 3) return false;
            c.A = g_q; c.wb = nwb0;
            if (a == 0) { c.use_ln = 1; c.g = ng + node * ISIZE; c.be = nbe + node * ISIZE;
                          c.bias = nb + (node * 4) * ISIZE; c.outh = g_Qh; c.outl = g_Ql; }
            else if (a == 1) { c.bias = nb + (node * 4) * ISIZE; c.outf = g_t0; }
            else { c.outf = g_t0; }
            return true;
        }
        if (z == 1) {
            if (a != 0 && a != 1 && a != 3 && a != 5) return false;
            c.A = g_k; c.wb = nwb0 + WELEM;
            if (a == 0) { c.bias = nb + (node * 4 + 1) * ISIZE; c.outh = g_Kh; c.outl = g_Kl; }
            else if (a == 1) { c.bias = nb + (node * 4 + 1) * ISIZE; c.outf = g_t1; }
            else if (a == 3) { c.outf = g_t1; }
            else { c.bias = nb + (node * 4 + 1) * ISIZE; c.actc = 2; c.outf = g_t1; }
            return true;
        }
        if (a != 0 && a != 3) return false;
        c.A = g_v; c.wb = nwb0 + 2 * WELEM;
        if (a == 0) { c.bias = nb + (node * 4 + 2) * ISIZE; c.outh = g_Vh; c.outl = g_Vl; }
        else { c.outf = g_t2; }
        return true;
    }
    if (a != 0 && a != 1 && a != 3) return false;
    c.wb = nwb0 + 3 * WELEM; c.bias = nb + (node * 4 + 3) * ISIZE;
    c.res = g_q; c.scale = r.aw; c.outf = g_outs[node];
    if (a == 0) c.A = g_t3;
    else if (a == 1) c.comb = 1;
    else c.comb = 2;
    return true;
}

// ---------------------------------------------------------------- fused stats+prep (+combine) -> xh/xl
__global__ void sp_kernel(int node, int set, const float* ie, const float* io,
        const float* eb, const float* eg, const float* ebe,
        const float* nb, const float* ng, const float* nbe) {
    int z = blockIdx.y;
    Cfg c;
    if (!resolve2(node, set, z, ie, io, eb, eg, ebe, nb, ng, nbe, c)) return;
    int row = blockIdx.x;
    size_t base = (size_t)row * ISIZE;
    if (c.copy) {
        #pragma unroll
        for (int t = 0; t < 4; t++) {
            int i = threadIdx.x + t * 128;
            c.outf[base + i] = c.scale * c.A[base + i];
        }
        return;
    }
    float x[4];
    #pragma unroll
    for (int t = 0; t < 4; t++) {
        int i = threadIdx.x + t * 128;
        if (c.comb == 1)      x[t] = gelu_f(g_t0[base + i]) * g_t1[base + i];
        else if (c.comb == 2) x[t] = fmaxf(g_t0[base + i] + g_t1[base + i] + g_t2[base + i], 0.f);
        else                  x[t] = c.A[base + i];
    }
    if (c.use_ln) {
        float s = x[0] + x[1] + x[2] + x[3];
        float s2 = x[0]*x[0] + x[1]*x[1] + x[2]*x[2] + x[3]*x[3];
        for (int o = 16; o; o >>= 1) {
            s += __shfl_down_sync(0xffffffffu, s, o);
            s2 += __shfl_down_sync(0xffffffffu, s2, o);
        }
        __shared__ float ra[4], rb[4];
        if ((threadIdx.x & 31) == 0) { ra[threadIdx.x >> 5] = s; rb[threadIdx.x >> 5] = s2; }
        __syncthreads();
        float S = ra[0] + ra[1] + ra[2] + ra[3];
        float S2 = rb[0] + rb[1] + rb[2] + rb[3];
        float m = S * (1.f / ISIZE);
        float var = S2 * (1.f / ISIZE) - m * m;
        if (var < 0.f) var = 0.f;
        float rs = rsqrtf(var + EPSF);
        #pragma unroll
        for (int t = 0; t < 4; t++) {
            int i = threadIdx.x + t * 128;
            x[t] = (x[t] - m) * rs * c.g[i] + c.be[i];
        }
    }
    #pragma unroll
    for (int t = 0; t < 4; t++) {
        int i = threadIdx.x + t * 128;
        __half h = __float2half_rn(x[t]);
        g_xh[z][base + i] = h;
        g_xl[z][base + i] = __float2half_rn(x[t] - __half2float(h));
    }
}

// ---------------------------------------------------------------- tensor-core GEMM (single-pass dual-half)
// C = A*W; per k-chunk cp.asyncs Ah,Al,Bh,Bl; 3 mma products per fragment pair.
// smem/stage: [Ah 8K][Al 8K][Bh 16K][Bl 16K] = 48K, double buffered = 96K dynamic.
__global__ void __launch_bounds__(256, 2) mma_gemm(int node, int set,
        const float* ie, const float* io,
        const float* eb, const float* eg, const float* ebe,
        const float* nb, const float* ng, const float* nbe) {
    int z = blockIdx.z;
    Cfg c;
    if (!resolve2(node, set, z, ie, io, eb, eg, ebe, nb, ng, nbe, c)) return;
    if (c.copy) return;

    extern __shared__ char dynsmem[];
    unsigned sb = (unsigned)__cvta_generic_to_shared(dynsmem);

    int tid = threadIdx.x;
    int lane = tid & 31, warp = tid >> 5;
    int wm = warp >> 2, wn = warp & 3;
    int m0 = blockIdx.y * 64, n0 = blockIdx.x * 128;

    const __half* Ah = g_xh[z];
    const __half* Al = g_xl[z];
    const __half* Wh = g_Wh + c.wb;
    const __half* Wl = g_Wl + c.wb;

    float acc[2][4][4];
    #pragma unroll
    for (int mt = 0; mt < 2; mt++)
        #pragma unroll
        for (int nt = 0; nt < 4; nt++)
            #pragma unroll
            for (int r = 0; r < 4; r++) acc[mt][nt][r] = 0.f;

    auto load_stage = [&](int it, int buf) {
        int kk = it * 64;
        unsigned da = sb + buf * 49152;
        unsigned db = da + 16384;
        #pragma unroll
        for (int j = 0; j < 2; j++) {
            int id = tid + j * 256;
            int row = id >> 3, ch = id & 7;
            unsigned off = (unsigned)((row * 8 + (ch ^ (row & 7))) * 16);
            size_t gidx = (size_t)(m0 + row) * ISIZE + kk + ch * 8;
            cp_async16(da + off, Ah + gidx);
            cp_async16(da + 8192 + off, Al + gidx);
        }
        #pragma unroll
        for (int j = 0; j < 4; j++) {
            int id = tid + j * 256;
            int row = id >> 4, ch = id & 15;
            unsigned off = (unsigned)((row * 16 + (ch ^ (row & 7))) * 16);
            size_t gidx = (size_t)(kk + row) * ISIZE + n0 + ch * 8;
            cp_async16(db + off, Wh + gidx);
            cp_async16(db + 16384 + off, Wl + gidx);
        }
        cp_commit();
    };

    auto compute = [&](int buf) {
        unsigned baA = sb + buf * 49152;
        unsigned baB = baA + 16384;
        #pragma unroll
        for (int s = 0; s < 4; s++) {
            unsigned aH[2][4], aL[2][4];
            #pragma unroll
            for (int mt = 0; mt < 2; mt++) {
                int r = wm * 32 + mt * 16 + (lane & 15);
                int ch = s * 2 + (lane >> 4);
                unsigned off = (unsigned)((r * 8 + (ch ^ (r & 7))) * 16);
                ldmx4(aH[mt], baA + off);
                ldmx4(aL[mt], baA + 8192 + off);
            }
            unsigned bH[4][2], bL[4][2];
            #pragma unroll
            for (int nt2 = 0; nt2 < 2; nt2++) {
                int k = s * 16 + (lane & 15);
                int ch = wn * 4 + nt2 * 2 + (lane >> 4);
                unsigned off = (unsigned)((k * 16 + (ch ^ (k & 7))) * 16);
                unsigned tmp[4];
                ldmx4t(tmp, baB + off);
                bH[nt2 * 2][0] = tmp[0]; bH[nt2 * 2][1] = tmp[1];
                bH[nt2 * 2 + 1][0] = tmp[2]; bH[nt2 * 2 + 1][1] = tmp[3];
                ldmx4t(tmp, baB + 16384 + off);
                bL[nt2 * 2][0] = tmp[0]; bL[nt2 * 2][1] = tmp[1];
                bL[nt2 * 2 + 1][0] = tmp[2]; bL[nt2 * 2 + 1][1] = tmp[3];
            }
            #pragma unroll
            for (int mt = 0; mt < 2; mt++)
                #pragma unroll
                for (int nt = 0; nt < 4; nt++) {
                    mma16816(acc[mt][nt], aH[mt], bH[nt]);
                    mma16816(acc[mt][nt], aL[mt], bH[nt]);
                    mma16816(acc[mt][nt], aH[mt], bL[nt]);
                }
        }
    };

    load_stage(0, 0);
    #pragma unroll 1
    for (int it = 0; it < 8; it++) {
        int buf = it & 1;
        if (it < 7) { load_stage(it + 1, buf ^ 1); cp_wait<1>(); }
        else cp_wait<0>();
        __syncthreads();
        compute(buf);
        __syncthreads();
    }

    #pragma unroll
    for (int mt = 0; mt < 2; mt++) {
        #pragma unroll
        for (int nt = 0; nt < 4; nt++) {
            #pragma unroll
            for (int r = 0; r < 4; r++) {
                int m = m0 + wm * 32 + mt * 16 + (lane >> 2) + ((r & 2) ? 8 : 0);
                int n = n0 + wn * 32 + nt * 8 + (lane & 3) * 2 + (r & 1);
                size_t idx = (size_t)m * ISIZE + n;
                float v = acc[mt][nt][r];
                if (c.bias) v += c.bias[n];
                if (c.actc == 1) v = fmaxf(v, 0.f);
                else if (c.actc == 2) v = gelu_f(v);
                if (c.outh) {
                    __half h = __float2half_rn(v);
                    c.outh[idx] = h;
                    c.outl[idx] = __float2half_rn(v - __half2float(h));
                } else {
                    if (c.res) v += c.res[idx];
                    c.outf[idx] = v * c.scale;
                }
            }
        }
    }
}

// ---------------------------------------------------------------- attention: scores (mma fp16x3)
__global__ void __launch_bounds__(256) attn_scores_mma(int node,
        const unsigned char* __restrict__ srcm, const unsigned char* __restrict__ tgtm) {
    const Route r = g_route[node];
    if (r.act != 0) return;
    int bh = blockIdx.z, b = bh >> 3, h = bh & 7;
    int q0 = blockIdx.y * 64, k0 = blockIdx.x * 128;

    __shared__ __half sQ[2][64 * 64];
    __shared__ __half sK[2][128 * 64];
    unsigned sq0 = (unsigned)__cvta_generic_to_shared(&sQ[0][0]);
    unsigned sk0 = (unsigned)__cvta_generic_to_shared(&sK[0][0]);

    int tid = threadIdx.x, lane = tid & 31, warp = tid >> 5;
    int wm = warp >> 2, wn = warp & 3;

    const __half* gq[2] = { g_Qh, g_Ql };
    const __half* gk[2] = { g_Kh, g_Kl };
    #pragma unroll
    for (int sp = 0; sp < 2; sp++) {
        #pragma unroll
        for (int j = 0; j < 2; j++) {
            int id = tid + j * 256;
            int row = id >> 3, ch = id & 7;
            const void* g = gq[sp] + (size_t)(b * SLEN + q0 + row) * ISIZE + h * 64 + ch * 8;
            cp_async16(sq0 + sp * 8192 + (unsigned)((row * 8 + (ch ^ (row & 7))) * 16), g);
        }
        #pragma unroll
        for (int j = 0; j < 4; j++) {
            int id = tid + j * 256;
            int row = id >> 3, ch = id & 7;
            const void* g = gk[sp] + (size_t)(b * SLEN + k0 + row) * ISIZE + h * 64 + ch * 8;
            cp_async16(sk0 + sp * 16384 + (unsigned)((row * 8 + (ch ^ (row & 7))) * 16), g);
        }
    }
    cp_commit(); cp_wait<0>();
    __syncthreads();

    float acc[2][4][4];
    #pragma unroll
    for (int mt = 0; mt < 2; mt++)
        #pragma unroll
        for (int nt = 0; nt < 4; nt++)
            #pragma unroll
            for (int rr = 0; rr < 4; rr++) acc[mt][nt][rr] = 0.f;

    #pragma unroll
    for (int ph = 0; ph < 3; ph++) {
        unsigned baQ = sq0 + ((ph == 1) ? 8192 : 0);
        unsigned baK = sk0 + ((ph == 2) ? 16384 : 0);
        #pragma unroll
        for (int s = 0; s < 4; s++) {
            unsigned af[2][4];
            #pragma unroll
            for (int mt = 0; mt < 2; mt++) {
                int rr = wm * 32 + mt * 16 + (lane & 15);
                int ch = s * 2 + (lane >> 4);
                ldmx4(af[mt], baQ + (unsigned)((rr * 8 + (ch ^ (rr & 7))) * 16));
            }
            unsigned bf[4][2];
            #pragma unroll
            for (int ng2 = 0; ng2 < 2; ng2++) {
                int nrow = wn * 32 + ng2 * 16 + (lane & 7) + ((lane >> 4) ? 8 : 0);
                int ch = s * 2 + ((lane >> 3) & 1);
                unsigned tmp[4];
                ldmx4(tmp, baK + (unsigned)((nrow * 8 + (ch ^ (nrow & 7))) * 16));
                bf[ng2 * 2][0] = tmp[0]; bf[ng2 * 2][1] = tmp[1];
                bf[ng2 * 2 + 1][0] = tmp[2]; bf[ng2 * 2 + 1][1] = tmp[3];
            }
            #pragma unroll
            for (int mt = 0; mt < 2; mt++)
                #pragma unroll
                for (int nt = 0; nt < 4; nt++)
                    mma16816(acc[mt][nt], af[mt], bf[nt]);
        }
    }

    const unsigned char* msk = (r.ktype == -1) ? tgtm : srcm;
    #pragma unroll
    for (int mt = 0; mt < 2; mt++) {
        #pragma unroll
        for (int nt = 0; nt < 4; nt++) {
            #pragma unroll
            for (int rr = 0; rr < 4; rr++) {
                int m = q0 + wm * 32 + mt * 16 + (lane >> 2) + ((rr & 2) ? 8 : 0);
                int n = k0 + wn * 32 + nt * 8 + (lane & 3) * 2 + (rr & 1);
                float s = acc[mt][nt][rr] * 0.125f;
                if (msk[b * SLEN + n]) s = -1e9f;
                g_scores[((size_t)bh << 20) + (size_t)m * SLEN + n] = s;
            }
        }
    }
}

// ---------------------------------------------------------------- softmax -> Ph/Pl
__global__ void __launch_bounds__(256) attn_softmax(int node) {
    if (g_route[node].act != 0) return;
    __shared__ float red[8];
    for (int row = blockIdx.x; row < BB * NHEAD * SLEN; row += gridDim.x) {
        const float* p = g_scores + (size_t)row * SLEN;
        float v[4];
        float mx = -1e30f;
        #pragma unroll
        for (int t = 0; t < 4; t++) {
            v[t] = p[threadIdx.x + t * 256];
            mx = fmaxf(mx, v[t]);
        }
        for (int o = 16; o; o >>= 1) mx = fmaxf(mx, __shfl_down_sync(0xffffffffu, mx, o));
        if ((threadIdx.x & 31) == 0) red[threadIdx.x >> 5] = mx;
        __syncthreads();
        float MX = red[0];
        #pragma unroll
        for (int w = 1; w < 8; w++) MX = fmaxf(MX, red[w]);
        __syncthreads();
        float s = 0.f;
        #pragma unroll
        for (int t = 0; t < 4; t++) { v[t] = expf(v[t] - MX); s += v[t]; }
        for (int o = 16; o; o >>= 1) s += __shfl_down_sync(0xffffffffu, s, o);
        if ((threadIdx.x & 31) == 0) red[threadIdx.x >> 5] = s;
        __syncthreads();
        float S = 0.f;
        #pragma unroll
        for (int w = 0; w < 8; w++) S += red[w];
        float inv = 1.f / S;
        #pragma unroll
        for (int t = 0; t < 4; t++) {
            float val = v[t] * inv;
            size_t idx = (size_t)row * SLEN + threadIdx.x + t * 256;
            __half hh = __float2half_rn(val);
            g_Ph[idx] = hh;
            g_Pl[idx] = __float2half_rn(val - __half2float(hh));
        }
        __syncthreads();
    }
}

// ---------------------------------------------------------------- attention: PV (mma fp16x3)
__global__ void __launch_bounds__(256) attn_pv_mma(int node) {
    const Route r = g_route[node];
    if (r.act != 0) return;
    int bh = blockIdx.y, b = bh >> 3, h = bh & 7;
    int q0 = blockIdx.x * 64;

    __shared__ __half sP[2][64 * 64];
    __shared__ __half sV[2][64 * 64];
    unsigned sp0 = (unsigned)__cvta_generic_to_shared(&sP[0][0]);
    unsigned sv0 = (unsigned)__cvta_generic_to_shared(&sV[0][0]);

    int tid = threadIdx.x, lane = tid & 31, warp = tid >> 5;
    int wm = warp >> 1, wn = warp & 1;

    const __half* gp[2] = { g_Ph + ((size_t)bh << 20), g_Pl + ((size_t)bh << 20) };
    const __half* gv[2] = { g_Vh, g_Vl };

    float acc[4][4];
    #pragma unroll
    for (int nt = 0; nt < 4; nt++)
        #pragma unroll
        for (int rr = 0; rr < 4; rr++) acc[nt][rr] = 0.f;

    for (int kt = 0; kt < 16; kt++) {
        #pragma unroll
        for (int sp = 0; sp < 2; sp++) {
            #pragma unroll
            for (int j = 0; j < 2; j++) {
                int id = tid + j * 256;
                int row = id >> 3, ch = id & 7;
                const void* g = gp[sp] + (size_t)(q0 + row) * SLEN + kt * 64 + ch * 8;
                cp_async16(sp0 + sp * 8192 + (unsigned)((row * 8 + (ch ^ (row & 7))) * 16), g);
            }
            #pragma unroll
            for (int j = 0; j < 2; j++) {
                int id = tid + j * 256;
                int row = id >> 3, ch = id & 7;
                const void* g = gv[sp] + (size_t)(b * SLEN + kt * 64 + row) * ISIZE + h * 64 + ch * 8;
                cp_async16(sv0 + sp * 8192 + (unsigned)((row * 8 + (ch ^ (row & 7))) * 16), g);
            }
        }
        cp_commit(); cp_wait<0>();
        __syncthreads();

        #pragma unroll
        for (int s = 0; s < 4; s++) {
            unsigned aH[4], aL[4];
            {
                int rr = wm * 16 + (lane & 15);
                int ch = s * 2 + (lane >> 4);
                unsigned off = (unsigned)((rr * 8 + (ch ^ (rr & 7))) * 16);
                ldmx4(aH, sp0 + off);
                ldmx4(aL, sp0 + 8192 + off);
            }
            unsigned bH[4][2], bL[4][2];
            #pragma unroll
            for (int nt2 = 0; nt2 < 2; nt2++) {
                int k = s * 16 + (lane & 15);
                int ch = wn * 4 + nt2 * 2 + (lane >> 4);
                unsigned off = (unsigned)((k * 8 + (ch ^ (k & 7))) * 16);
                unsigned tmp[4];
                ldmx4t(tmp, sv0 + off);
                bH[nt2 * 2][0] = tmp[0]; bH[nt2 * 2][1] = tmp[1];
                bH[nt2 * 2 + 1][0] = tmp[2]; bH[nt2 * 2 + 1][1] = tmp[3];
                ldmx4t(tmp, sv0 + 8192 + off);
                bL[nt2 * 2][0] = tmp[0]; bL[nt2 * 2][1] = tmp[1];
                bL[nt2 * 2 + 1][0] = tmp[2]; bL[nt2 * 2 + 1][1] = tmp[3];
            }
            #pragma unroll
            for (int nt = 0; nt < 4; nt++) {
                mma16816(acc[nt], aH, bH[nt]);
                mma16816(acc[nt], aL, bH[nt]);
                mma16816(acc[nt], aH, bL[nt]);
            }
        }
        __syncthreads();
    }

    #pragma unroll
    for (int nt = 0; nt < 4; nt++) {
        #pragma unroll
        for (int rr = 0; rr < 4; rr++) {
            int m = q0 + wm * 16 + (lane >> 2) + ((rr & 2) ? 8 : 0);
            int n = wn * 32 + nt * 8 + (lane & 3) * 2 + (rr & 1);
            g_t3[(size_t)(b * SLEN + m) * ISIZE + h * 64 + n] = acc[nt][rr];
        }
    }
}

// ---------------------------------------------------------------- elementwise final (acts 2,4,5,6,7)
__global__ void ew_final(int node, const float* ng, const float* nbe) {
    const Route r = g_route[node];
    int a = r.act;
    if (a == 0 || a == 1 || a == 3) return;
    int row = blockIdx.x;
    size_t base = (size_t)row * ISIZE;
    float* out = g_outs[node];
    if (a == 4 || a == 5 || a == 6) {
        for (int i = threadIdx.x; i < ISIZE; i += 128) {
            size_t idx = base + i;
            float q = g_q[idx];
            float v;
            if (a == 4) v = q * (1.f / (1.f + expf(-g_k[idx]))) + g_v[idx];
            else if (a == 5) v = q + g_t1[idx];
            else v = q + g_k[idx];
            out[idx] = r.aw * v;
        }
        return;
    }
    float vals[4];
    float s = 0.f, s2 = 0.f;
    #pragma unroll
    for (int t = 0; t < 4; t++) {
        int i = threadIdx.x + t * 128;
        size_t idx = base + i;
        float x = (a == 2) ? (g_q[idx] + g_k[idx] + g_v[idx]) : g_q[idx];
        vals[t] = x; s += x; s2 += x * x;
    }
    for (int o = 16; o; o >>= 1) {
        s += __shfl_down_sync(0xffffffffu, s, o);
        s2 += __shfl_down_sync(0xffffffffu, s2, o);
    }
    __shared__ float ra[4], rb[4];
    if ((threadIdx.x & 31) == 0) { ra[threadIdx.x >> 5] = s; rb[threadIdx.x >> 5] = s2; }
    __syncthreads();
    float S = ra[0] + ra[1] + ra[2] + ra[3];
    float S2 = rb[0] + rb[1] + rb[2] + rb[3];
    float m = S * (1.f / ISIZE);
    float var = S2 * (1.f / ISIZE) - m * m;
    if (var < 0.f) var = 0.f;
    float rs = rsqrtf(var + EPSF);
    #pragma unroll
    for (int t = 0; t < 4; t++) {
        int i = threadIdx.x + t * 128;
        out[base + i] = r.aw * ((vals[t] - m) * rs * ng[node * ISIZE + i] + nbe[node * ISIZE + i]);
    }
}

// ---------------------------------------------------------------- final sum + LN
__global__ void final_kernel(const float* og, const float* obe, float* out) {
    int row = blockIdx.x;
    size_t base = (size_t)row * ISIZE;
    float vals[4];
    float s = 0.f, s2 = 0.f;
    #pragma unroll
    for (int t = 0; t < 4; t++) {
        int i = threadIdx.x + t * 128;
        float x = 0.f;
        for (int n = 0; n < NNOD; n++)
            if (!g_proc[n]) x += g_outs[n][base + i];
        vals[t] = x; s += x; s2 += x * x;
    }
    for (int o = 16; o; o >>= 1) {
        s += __shfl_down_sync(0xffffffffu, s, o);
        s2 += __shfl_down_sync(0xffffffffu, s2, o);
    }
    __shared__ float ra[4], rb[4];
    if ((threadIdx.x & 31) == 0) { ra[threadIdx.x >> 5] = s; rb[threadIdx.x >> 5] = s2; }
    __syncthreads();
    float S = ra[0] + ra[1] + ra[2] + ra[3];
    float S2 = rb[0] + rb[1] + rb[2] + rb[3];
    float m = S * (1.f / ISIZE);
    float var = S2 * (1.f / ISIZE) - m * m;
    if (var < 0.f) var = 0.f;
    float rs = rsqrtf(var + EPSF);
    #pragma unroll
    for (int t = 0; t < 4; t++) {
        int i = threadIdx.x + t * 128;
        out[base + i] = (vals[t] - m) * rs * og[i] + obe[i];
    }
}

// ---------------------------------------------------------------- launch
extern "C" void kernel_launch(void* const* d_in, const int* in_sizes, int n_in,
                              void* d_out, int out_size) {
    const float* ie  = (const float*)d_in[0];
    const float* io  = (const float*)d_in[1];
    const float* npw = (const float*)d_in[2];
    const float* epw = (const float*)d_in[3];
    const float* eW  = (const float*)d_in[4];
    const float* eb  = (const float*)d_in[5];
    const float* eg  = (const float*)d_in[6];
    const float* ebe = (const float*)d_in[7];
    const float* nW  = (const float*)d_in[8];
    const float* nb  = (const float*)d_in[9];
    const float* ng  = (const float*)d_in[10];
    const float* nbe = (const float*)d_in[11];
    const float* og  = (const float*)d_in[12];
    const float* obe = (const float*)d_in[13];
    const unsigned char* srcm = (const unsigned char*)d_in[14];
    const unsigned char* tgtm = (const unsigned char*)d_in[15];
    float* out = (float*)d_out;

    cudaFuncSetAttribute(mma_gemm, cudaFuncAttributeMaxDynamicSharedMemorySize, GEMM_SMEM);

    route_kernel<<<1, 32>>>(npw, epw);
    wsplit_kernel<<<dim3(64, NMAT), 256>>>(eW, nW);

    dim3 gg3(ISIZE / 128, NROWS / 64, 3);
    dim3 gg1(ISIZE / 128, NROWS / 64, 1);
    for (int c = 0; c < NNOD; c++) {
        sp_kernel<<<dim3(NROWS, 3), 128>>>(c, 0, ie, io, eb, eg, ebe, nb, ng, nbe);
        mma_gemm<<<gg3, 256, GEMM_SMEM>>>(c, 0, ie, io, eb, eg, ebe, nb, ng, nbe);
        sp_kernel<<<dim3(NROWS, 3), 128>>>(c, 1, ie, io, eb, eg, ebe, nb, ng, nbe);
        mma_gemm<<<gg3, 256, GEMM_SMEM>>>(c, 1, ie, io, eb, eg, ebe, nb, ng, nbe);
        attn_scores_mma<<<dim3(8, 16, 32), 256>>>(c, srcm, tgtm);
        attn_softmax<<<4096, 256>>>(c);
        attn_pv_mma<<<dim3(16, 32), 256>>>(c);
        sp_kernel<<<dim3(NROWS, 1), 128>>>(c, 2, ie, io, eb, eg, ebe, nb, ng, nbe);
        mma_gemm<<<gg1, 256, GEMM_SMEM>>>(c, 2, ie, io, eb, eg, ebe, nb, ng, nbe);
        ew_final<<<NROWS, 128>>>(c, ng, nbe);
    }
    final_kernel<<<NROWS, 128>>>(og, obe, out);
}